// round 12
// baseline (speedup 1.0000x reference)
#include <cuda_runtime.h>
#include <cuda_fp16.h>
#include <float.h>

#define CCH   512
#define HH    38
#define WW    63
#define HWN   (HH*WW)          /* 2394 */
#define NROI  1024
#define PRE   14               /* pre-pool grid 14x14 */
#define PS    7
#define TSTRIDE 257            /* 256 half2-words + 1 pad: conflict-free flush */
#define SMEM_BYTES (49*TSTRIDE*4)  /* 50372 B */

// HWC-transposed fp16 feature map scratch (2.45 MB, L2-resident).
__device__ __half g_hwc_h[HWN * CCH];

// ---------------------------------------------------------------------------
// Kernel 1: CHW f32 -> HWC f16 transpose (tiled, conflict-free)
// ---------------------------------------------------------------------------
__global__ void transpose_kernel(const float* __restrict__ src) {
    __shared__ float t[32][33];
    int hw0 = blockIdx.x * 32;
    int c0  = blockIdx.y * 32;

    int hw = hw0 + threadIdx.x;
#pragma unroll
    for (int dy = 0; dy < 32; dy += 8) {
        int c = c0 + threadIdx.y + dy;
        if (hw < HWN && c < CCH)
            t[threadIdx.y + dy][threadIdx.x] = src[c * HWN + hw];
    }
    __syncthreads();

    int c2 = c0 + threadIdx.x;
#pragma unroll
    for (int dy = 0; dy < 32; dy += 8) {
        int hh = hw0 + threadIdx.y + dy;
        if (hh < HWN && c2 < CCH)
            g_hwc_h[hh * CCH + c2] = __float2half_rn(t[threadIdx.x][threadIdx.y + dy]);
    }
}

// ---------------------------------------------------------------------------
// 4 channels as 2x half2 (lean live set -> 42-reg budget for 3 CTAs/SM)
struct H4 { __half2 a, b; };

__device__ __forceinline__ H4 lerpH(H4 p, H4 q, __half2 w) {
    H4 r;
    r.a = __hfma2(__hsub2(q.a, p.a), w, p.a);
    r.b = __hfma2(__hsub2(q.b, p.b), w, p.b);
    return r;
}
// running max with half2 0/1 mask applied via HMUL2 (fma pipe)
__device__ __forceinline__ void maxH(H4& m, H4 v, __half2 mk) {
    m.a = __hmax2(m.a, __hmul2(v.a, mk));
    m.b = __hmax2(m.b, __hmul2(v.b, mk));
}

// ---------------------------------------------------------------------------
// Kernel 2: per-roi crop-and-resize (bilinear 14x14) + 2x2 maxpool -> 7x7.
// 4 groups x 128 lanes; lane owns 4 consecutive channels (one LDG.64 per
// corner). Packed half2 math; half2 staging; f32 conversion in the flush.
// 3 CTAs/SM (42-reg budget) for latency hiding.
// ---------------------------------------------------------------------------
__global__ __launch_bounds__(512, 3)
void roi_kernel(const float* __restrict__ rois, float* __restrict__ out) {
    extern __shared__ unsigned tile_u[];      // [49][TSTRIDE] half2 words

    // stage-1: per-sample
    __shared__ int     sy0[PRE], sy1[PRE], sx0[PRE], sx1[PRE];
    __shared__ float   swx_f[PRE];
    __shared__ __half2 swy[PRE];
    __shared__ unsigned svy[PRE], svx[PRE];   // 0x3C003C00 (1.0h2) or 0
    // stage-2: per pooled cell (premultiplied offsets in uint2/4-channel units)
    __shared__ int     yR0[PS], yR1[PS], yR2[PS], yR3[PS], yCs[PS];
    __shared__ unsigned yVa[PS], yVb[PS];
    __shared__ int     xC0[PS], xC1[PS], xC2[PS], xC3[PS], xCs[PS];
    __shared__ __half2 xWa[PS], xWb[PS];
    __shared__ unsigned xVa[PS], xVb[PS];

    const int r   = blockIdx.x;
    const int tid = threadIdx.x;

    // --- stage 1: per-axis sample coords / weights / validity (ref math) ---
    if (tid < 2 * PRE) {
        bool isx = tid >= PRE;
        int  i   = isx ? tid - PRE : tid;
        float lo    = rois[5 * r + (isx ? 1 : 2)];
        float hi    = rois[5 * r + (isx ? 3 : 4)];
        float dimm1 = isx ? (float)(WW - 1) : (float)(HH - 1);
        float an = lo * 0.0625f / dimm1;
        float bn = hi * 0.0625f / dimm1;
        float t  = (float)i / 13.0f;
        float v  = (an + t * (bn - an)) * dimm1;
        float f  = floorf(v);
        int p0   = (int)f;
        int lim  = (int)dimm1;
        int q0   = min(max(p0, 0), lim);
        int q1   = min(max(p0 + 1, 0), lim);
        float w  = v - f;
        unsigned ok = (v >= 0.0f && v <= dimm1) ? 0x3C003C00u : 0u;  // half2 1/0
        if (isx) { sx0[i] = q0; sx1[i] = q1; swx_f[i] = w; svx[i] = ok; }
        else     { sy0[i] = q0; sy1[i] = q1;
                   swy[i] = __float2half2_rn(w); svy[i] = ok; }
    }
    __syncthreads();

    // --- stage 2: per pooled cell structure + dedup case codes ---
    if (tid < 2 * PS) {
        bool isx = tid >= PS;
        int  q   = isx ? tid - PS : tid;
        int  i = 2 * q, j = 2 * q + 1;
        if (!isx) {
            int R0 = sy0[i], R1 = sy1[i], R2 = sy0[j], R3 = sy1[j];
            yCs[q] = (R2 == R0) ? 0 : ((R2 == R1) ? 1 : 2);
            yR0[q] = R0 * (WW * 128); yR1[q] = R1 * (WW * 128);
            yR2[q] = R2 * (WW * 128); yR3[q] = R3 * (WW * 128);
            yVa[q] = svy[i]; yVb[q] = svy[j];
        } else {
            int C0 = sx0[i], C1 = sx1[i], C2 = sx0[j], C3 = sx1[j];
            xCs[q] = (C2 == C0) ? 0 : ((C2 == C1) ? 1 : 2);
            xC0[q] = C0 * 128; xC1[q] = C1 * 128;
            xC2[q] = C2 * 128; xC3[q] = C3 * 128;
            xWa[q] = __float2half2_rn(swx_f[i]);
            xWb[q] = __float2half2_rn(swx_f[j]);
            xVa[q] = svx[i]; xVb[q] = svx[j];
        }
    }
    __syncthreads();

    const int c4 = tid & 127;                     // 4-channel lane index
    const uint2* __restrict__ base = (const uint2*)g_hwc_h + c4;

    auto ldc = [&](int off) -> H4 {
        uint2 g = base[off];
        H4 h;
        h.a = reinterpret_cast<__half2&>(g.x);
        h.b = reinterpret_cast<__half2&>(g.y);
        return h;
    };

    const unsigned NEGINF2 = 0xFC00FC00u;         // half2(-inf,-inf)

    int pos = tid >> 7;      // group 0..3
    int py  = 0;
    int px  = pos;
    while (pos < 49) {
        const int     c0 = xC0[px], c1 = xC1[px], c2 = xC2[px], c3 = xC3[px];
        const int     xcs = xCs[px];
        const __half2 wxa = xWa[px], wxb = xWb[px];
        const int     r0 = yR0[py], r1 = yR1[py], r2 = yR2[py], r3 = yR3[py];
        const int     ycs = yCs[py];
        const __half2 wya = swy[2 * py], wyb = swy[2 * py + 1];
        // 0/1 half2 masks via HMUL2 (fma pipe)
        const __half2 mya = reinterpret_cast<const __half2&>(yVa[py]);
        const __half2 myb = reinterpret_cast<const __half2&>(yVb[py]);
        const __half2 mxa = reinterpret_cast<const __half2&>(xVa[px]);
        const __half2 mxb = reinterpret_cast<const __half2&>(xVb[px]);
        const __half2 maa = __hmul2(mya, mxa);
        const __half2 mab = __hmul2(mya, mxb);
        const __half2 mba = __hmul2(myb, mxa);
        const __half2 mbb = __hmul2(myb, mxb);

        // horizontal interp for one row, deduping shared columns (uniform branch)
        auto hx_row = [&](int roff, H4& ha, H4& hb) {
            if (xcs == 0) {             // 2 unique cols
                H4 g0 = ldc(roff + c0);
                H4 g1 = ldc(roff + c1);
                ha = lerpH(g0, g1, wxa);
                hb = lerpH(g0, g1, wxb);
            } else if (xcs == 1) {      // 3 unique cols
                H4 g0 = ldc(roff + c0);
                H4 g1 = ldc(roff + c1);
                H4 g3 = ldc(roff + c3);
                ha = lerpH(g0, g1, wxa);
                hb = lerpH(g1, g3, wxb);
            } else {                    // 4 unique cols
                H4 g0 = ldc(roff + c0);
                H4 g1 = ldc(roff + c1);
                H4 g2 = ldc(roff + c2);
                H4 g3 = ldc(roff + c3);
                ha = lerpH(g0, g1, wxa);
                hb = lerpH(g2, g3, wxb);
            }
        };

        H4 m;
        m.a = reinterpret_cast<const __half2&>(NEGINF2);
        m.b = m.a;

        H4 h0a, h0b, h1a, h1b;
        hx_row(r0, h0a, h0b);
        hx_row(r1, h1a, h1b);
        maxH(m, lerpH(h0a, h1a, wya), maa);
        maxH(m, lerpH(h0b, h1b, wya), mab);

        H4 h2a, h2b, h3a, h3b;
        if (ycs == 0) {                 // reuse both rows
            h2a = h0a; h2b = h0b; h3a = h1a; h3b = h1b;
        } else if (ycs == 1) {          // reuse one row
            h2a = h1a; h2b = h1b;
            hx_row(r3, h3a, h3b);
        } else {
            hx_row(r2, h2a, h2b);
            hx_row(r3, h3a, h3b);
        }
        maxH(m, lerpH(h2a, h3a, wyb), mba);
        maxH(m, lerpH(h2b, h3b, wyb), mbb);

        // stage half2 words: pair P = 2*c4 + w  ->  col = c4 + 128*w
        unsigned* st = tile_u + pos * TSTRIDE + c4;
        st[0]   = reinterpret_cast<unsigned&>(m.a);
        st[128] = reinterpret_cast<unsigned&>(m.b);

        pos += 4;
        px  += 4;
        if (px >= 7) { px -= 7; ++py; }
    }
    __syncthreads();

    // --- flush by channel pairs: word (P,pos) -> out[2P*49+pos], [..+49] ---
    // col(P) = (P>>1) + ((P&1)<<7); reads bank-stride 1; STG coalesced.
    float* __restrict__ dst = out + (size_t)r * (CCH * 49);
    int k = tid;
    int P = tid / 49;
    int pos2 = tid - P * 49;
    while (k < 256 * 49) {
        int col = (P >> 1) + ((P & 1) << 7);
        unsigned w = tile_u[pos2 * TSTRIDE + col];
        float2 f = __half22float2(reinterpret_cast<__half2&>(w));
        int o = P * 98 + pos2;
        dst[o]      = f.x;
        dst[o + 49] = f.y;
        k += 512; pos2 += 22; P += 10;    // 512 = 10*49 + 22
        if (pos2 >= 49) { pos2 -= 49; ++P; }
    }
}

// ---------------------------------------------------------------------------
extern "C" void kernel_launch(void* const* d_in, const int* in_sizes, int n_in,
                              void* d_out, int out_size) {
    const float* bottom;
    const float* rois;
    if (n_in >= 2 && in_sizes[0] == 5 * NROI) {
        rois   = (const float*)d_in[0];
        bottom = (const float*)d_in[1];
    } else {
        bottom = (const float*)d_in[0];
        rois   = (const float*)d_in[1];
    }
    float* out = (float*)d_out;

    cudaFuncSetAttribute(roi_kernel,
                         cudaFuncAttributeMaxDynamicSharedMemorySize, SMEM_BYTES);

    dim3 tb(32, 8);
    dim3 tg((HWN + 31) / 32, (CCH + 31) / 32);
    transpose_kernel<<<tg, tb>>>(bottom);
    roi_kernel<<<NROI, 512, SMEM_BYTES>>>(rois, out);
}

// round 13
// speedup vs baseline: 1.1933x; 1.1933x over previous
#include <cuda_runtime.h>
#include <cuda_fp16.h>
#include <float.h>

#define CCH   512
#define HH    38
#define WW    63
#define HWN   (HH*WW)          /* 2394 */
#define NROI  1024
#define PRE   14               /* pre-pool grid 14x14 */
#define PS    7
#define TSTRIDE 257            /* 256 half2-words + 1 pad: conflict-free flush */
#define SMEM_BYTES (49*TSTRIDE*4)  /* 50372 B */

// HWC-transposed fp16 feature map scratch (2.45 MB, L2-resident).
__device__ __half g_hwc_h[HWN * CCH];

// ---------------------------------------------------------------------------
// Kernel 1: CHW f32 -> HWC f16 transpose; packs 2 channels per 32-bit store.
// ---------------------------------------------------------------------------
__global__ void transpose_kernel(const float* __restrict__ src) {
    __shared__ float t[32][33];
    int hw0 = blockIdx.x * 32;
    int c0  = blockIdx.y * 32;

    int hw = hw0 + threadIdx.x;
#pragma unroll
    for (int dy = 0; dy < 32; dy += 8) {
        int c = c0 + threadIdx.y + dy;
        if (hw < HWN && c < CCH)
            t[threadIdx.y + dy][threadIdx.x] = src[c * HWN + hw];
    }
    __syncthreads();

    // write phase: 32 hw x 16 half2-words per tile; consecutive threads ->
    // consecutive words (coalesced 32-bit stores)
    unsigned* __restrict__ dstw = reinterpret_cast<unsigned*>(g_hwc_h);
    int lin = threadIdx.y * 32 + threadIdx.x;       // 0..255
#pragma unroll
    for (int j = lin; j < 512; j += 256) {
        int wc  = j & 15;                           // word-col within tile
        int hhl = j >> 4;                           // hw within tile
        int hh  = hw0 + hhl;
        if (hh < HWN) {
            __half2 v = __floats2half2_rn(t[2 * wc][hhl], t[2 * wc + 1][hhl]);
            dstw[hh * (CCH / 2) + (c0 >> 1) + wc] = reinterpret_cast<unsigned&>(v);
        }
    }
}

// ---------------------------------------------------------------------------
// 8 channels as 4x half2
struct H8 { __half2 a, b, c, d; };

__device__ __forceinline__ H8 lerpH(H8 p, H8 q, __half2 w) {
    H8 r;
    r.a = __hfma2(__hsub2(q.a, p.a), w, p.a);
    r.b = __hfma2(__hsub2(q.b, p.b), w, p.b);
    r.c = __hfma2(__hsub2(q.c, p.c), w, p.c);
    r.d = __hfma2(__hsub2(q.d, p.d), w, p.d);
    return r;
}
// running max with half2 0/1 mask applied via HMUL2 (fma pipe)
__device__ __forceinline__ void maxH(H8& m, H8 v, __half2 mk) {
    m.a = __hmax2(m.a, __hmul2(v.a, mk));
    m.b = __hmax2(m.b, __hmul2(v.b, mk));
    m.c = __hmax2(m.c, __hmul2(v.c, mk));
    m.d = __hmax2(m.d, __hmul2(v.d, mk));
}

// ---------------------------------------------------------------------------
// Kernel 2: per-roi crop-and-resize (bilinear 14x14) + 2x2 maxpool -> 7x7.
// 8 groups x 64 lanes; lane owns 8 consecutive channels (LDG.128 per corner).
// Packed half2 math, half2 staging, f32 conversion in the coalesced flush.
// ---------------------------------------------------------------------------
__global__ __launch_bounds__(512, 2)
void roi_kernel(const float* __restrict__ rois, float* __restrict__ out) {
    extern __shared__ unsigned tile_u[];      // [49][TSTRIDE] half2 words

    // stage-1: per-sample
    __shared__ int     sy0[PRE], sy1[PRE], sx0[PRE], sx1[PRE];
    __shared__ float   swx_f[PRE];
    __shared__ __half2 swy[PRE];
    __shared__ unsigned svy[PRE], svx[PRE];   // 0x3C003C00 (1.0h2) or 0
    // stage-2: per pooled cell (premultiplied offsets in uint4/8-channel units)
    __shared__ int     yR0[PS], yR1[PS], yR2[PS], yR3[PS], yCs[PS];
    __shared__ unsigned yVa[PS], yVb[PS];
    __shared__ int     xC0[PS], xC1[PS], xC2[PS], xC3[PS], xCs[PS];
    __shared__ __half2 xWa[PS], xWb[PS];
    __shared__ unsigned xVa[PS], xVb[PS];

    const int r   = blockIdx.x;
    const int tid = threadIdx.x;

    // --- stage 1 (warp 0): per-axis coords / weights / validity (ref math) ---
    if (tid < 32) {
        if (tid < 2 * PRE) {
            bool isx = tid >= PRE;
            int  i   = isx ? tid - PRE : tid;
            float lo    = rois[5 * r + (isx ? 1 : 2)];
            float hi    = rois[5 * r + (isx ? 3 : 4)];
            float dimm1 = isx ? (float)(WW - 1) : (float)(HH - 1);
            float an = lo * 0.0625f / dimm1;
            float bn = hi * 0.0625f / dimm1;
            float t  = (float)i / 13.0f;
            float v  = (an + t * (bn - an)) * dimm1;
            float f  = floorf(v);
            int p0   = (int)f;
            int lim  = (int)dimm1;
            int q0   = min(max(p0, 0), lim);
            int q1   = min(max(p0 + 1, 0), lim);
            float w  = v - f;
            unsigned ok = (v >= 0.0f && v <= dimm1) ? 0x3C003C00u : 0u;
            if (isx) { sx0[i] = q0; sx1[i] = q1; swx_f[i] = w; svx[i] = ok; }
            else     { sy0[i] = q0; sy1[i] = q1;
                       swy[i] = __float2half2_rn(w); svy[i] = ok; }
        }
        __syncwarp();
        // --- stage 2 (warp 0): per pooled cell structure + dedup codes ---
        if (tid < 2 * PS) {
            bool isx = tid >= PS;
            int  q   = isx ? tid - PS : tid;
            int  i = 2 * q, j = 2 * q + 1;
            if (!isx) {
                int R0 = sy0[i], R1 = sy1[i], R2 = sy0[j], R3 = sy1[j];
                yCs[q] = (R2 == R0) ? 0 : ((R2 == R1) ? 1 : 2);
                yR0[q] = R0 * (WW * 64); yR1[q] = R1 * (WW * 64);
                yR2[q] = R2 * (WW * 64); yR3[q] = R3 * (WW * 64);
                yVa[q] = svy[i]; yVb[q] = svy[j];
            } else {
                int C0 = sx0[i], C1 = sx1[i], C2 = sx0[j], C3 = sx1[j];
                xCs[q] = (C2 == C0) ? 0 : ((C2 == C1) ? 1 : 2);
                xC0[q] = C0 * 64; xC1[q] = C1 * 64;
                xC2[q] = C2 * 64; xC3[q] = C3 * 64;
                xWa[q] = __float2half2_rn(swx_f[i]);
                xWb[q] = __float2half2_rn(swx_f[j]);
                xVa[q] = svx[i]; xVb[q] = svx[j];
            }
        }
    }
    __syncthreads();

    const int c8 = tid & 63;                      // 8-channel lane index
    const uint4* __restrict__ base = (const uint4*)g_hwc_h + c8;

    auto ldc = [&](int off) -> H8 {
        uint4 g = base[off];
        H8 h;
        h.a = reinterpret_cast<__half2&>(g.x);
        h.b = reinterpret_cast<__half2&>(g.y);
        h.c = reinterpret_cast<__half2&>(g.z);
        h.d = reinterpret_cast<__half2&>(g.w);
        return h;
    };

    const unsigned NEGINF2 = 0xFC00FC00u;         // half2(-inf,-inf)

    int pos = tid >> 6;      // group 0..7
    int py  = pos / 7;       // 0 (or 1 for g=7)
    int px  = pos - py * 7;
    while (pos < 49) {
        const int     c0 = xC0[px], c1 = xC1[px], c2 = xC2[px], c3 = xC3[px];
        const int     xcs = xCs[px];
        const __half2 wxa = xWa[px], wxb = xWb[px];
        const int     r0 = yR0[py], r1 = yR1[py], r2 = yR2[py], r3 = yR3[py];
        const int     ycs = yCs[py];
        const __half2 wya = swy[2 * py], wyb = swy[2 * py + 1];
        const __half2 mya = reinterpret_cast<const __half2&>(yVa[py]);
        const __half2 myb = reinterpret_cast<const __half2&>(yVb[py]);
        const __half2 mxa = reinterpret_cast<const __half2&>(xVa[px]);
        const __half2 mxb = reinterpret_cast<const __half2&>(xVb[px]);
        const __half2 maa = __hmul2(mya, mxa);
        const __half2 mab = __hmul2(mya, mxb);
        const __half2 mba = __hmul2(myb, mxa);
        const __half2 mbb = __hmul2(myb, mxb);

        // horizontal interp for one row, deduping shared columns (uniform branch)
        auto hx_row = [&](int roff, H8& ha, H8& hb) {
            if (xcs == 0) {             // 2 unique cols
                H8 g0 = ldc(roff + c0);
                H8 g1 = ldc(roff + c1);
                ha = lerpH(g0, g1, wxa);
                hb = lerpH(g0, g1, wxb);
            } else if (xcs == 1) {      // 3 unique cols
                H8 g0 = ldc(roff + c0);
                H8 g1 = ldc(roff + c1);
                H8 g3 = ldc(roff + c3);
                ha = lerpH(g0, g1, wxa);
                hb = lerpH(g1, g3, wxb);
            } else {                    // 4 unique cols
                H8 g0 = ldc(roff + c0);
                H8 g1 = ldc(roff + c1);
                H8 g2 = ldc(roff + c2);
                H8 g3 = ldc(roff + c3);
                ha = lerpH(g0, g1, wxa);
                hb = lerpH(g2, g3, wxb);
            }
        };

        H8 m;
        m.a = reinterpret_cast<const __half2&>(NEGINF2);
        m.b = m.a; m.c = m.a; m.d = m.a;

        H8 h0a, h0b, h1a, h1b;
        hx_row(r0, h0a, h0b);
        hx_row(r1, h1a, h1b);
        maxH(m, lerpH(h0a, h1a, wya), maa);
        maxH(m, lerpH(h0b, h1b, wya), mab);

        H8 h2a, h2b, h3a, h3b;
        if (ycs == 0) {                 // reuse both rows
            h2a = h0a; h2b = h0b; h3a = h1a; h3b = h1b;
        } else if (ycs == 1) {          // reuse one row
            h2a = h1a; h2b = h1b;
            hx_row(r3, h3a, h3b);
        } else {
            hx_row(r2, h2a, h2b);
            hx_row(r3, h3a, h3b);
        }
        maxH(m, lerpH(h2a, h3a, wyb), mba);
        maxH(m, lerpH(h2b, h3b, wyb), mbb);

        // stage half2 words: word col = c8 + 64*w holds channels 8c8+2w, +1
        unsigned* st = tile_u + pos * TSTRIDE + c8;
        st[0]   = reinterpret_cast<unsigned&>(m.a);
        st[64]  = reinterpret_cast<unsigned&>(m.b);
        st[128] = reinterpret_cast<unsigned&>(m.c);
        st[192] = reinterpret_cast<unsigned&>(m.d);

        pos += 8;
        px  += 1;
        py  += 1;
        if (px >= 7) { px -= 7; ++py; }
    }
    __syncthreads();

    // --- flush by channel pairs: word (P,pos) -> out[2P*49+pos], [..+49] ---
    // col(P) = (P>>2) + ((P&3)<<6); reads bank-stride 1; STG coalesced.
    float* __restrict__ dst = out + (size_t)r * (CCH * 49);
    int k = tid;
    int P = tid / 49;
    int pos2 = tid - P * 49;
    while (k < 256 * 49) {
        int col = (P >> 2) + ((P & 3) << 6);
        unsigned w = tile_u[pos2 * TSTRIDE + col];
        float2 f = __half22float2(reinterpret_cast<__half2&>(w));
        int o = P * 98 + pos2;
        dst[o]      = f.x;
        dst[o + 49] = f.y;
        k += 512; pos2 += 22; P += 10;    // 512 = 10*49 + 22
        if (pos2 >= 49) { pos2 -= 49; ++P; }
    }
}

// ---------------------------------------------------------------------------
extern "C" void kernel_launch(void* const* d_in, const int* in_sizes, int n_in,
                              void* d_out, int out_size) {
    const float* bottom;
    const float* rois;
    if (n_in >= 2 && in_sizes[0] == 5 * NROI) {
        rois   = (const float*)d_in[0];
        bottom = (const float*)d_in[1];
    } else {
        bottom = (const float*)d_in[0];
        rois   = (const float*)d_in[1];
    }
    float* out = (float*)d_out;

    cudaFuncSetAttribute(roi_kernel,
                         cudaFuncAttributeMaxDynamicSharedMemorySize, SMEM_BYTES);

    dim3 tb(32, 8);
    dim3 tg((HWN + 31) / 32, (CCH + 31) / 32);
    transpose_kernel<<<tg, tb>>>(bottom);
    roi_kernel<<<NROI, 512, SMEM_BYTES>>>(rois, out);
}